// round 11
// baseline (speedup 1.0000x reference)
#include <cuda_runtime.h>
#include <cuda_bf16.h>
#include <cstdint>

#define HH 300
#define G4 1200
#define NTW 192                 // 6 warps: one weight tile each

// SMEM offsets (bytes)
#define SM_A    0               // 6 tiles x 19456 = 116736
#define SM_HSTH 116736          // staging hi: 8 rows x 608
#define SM_HSTL 121600          // staging lo
#define SM_C    126464          // c-state: 24 units x 128 rows x f32 = 12288
#define SM_TOT  138752

__device__ __align__(256) float Wt2_g[600 * G4];   // step0 weights [k][u*4+g]
__device__ __align__(256) float Wc2_g[HH * G4];    // folded [k][u*4+g]
__device__ __align__(256) float bias2_g[G4];
__device__ __align__(256) float biasf_g[G4];
__device__ __align__(256) __nv_bfloat16 AT_g[96 * 9728];  // [tile][kt][hl][r16][k16]
__device__ float c1_g[1024 * HH];
__device__ float hP0_g[1024 * HH];
__device__ float hP1_g[1024 * HH];
__device__ unsigned bar_cnt_g;

__device__ __forceinline__ uint32_t smem_u32(const void* p) {
    uint32_t a;
    asm("{ .reg .u64 t; cvta.to.shared.u64 t, %1; cvt.u32.u64 %0, t; }" : "=r"(a) : "l"(p));
    return a;
}
__device__ __forceinline__ float sigf(float x) {
    return __fdividef(1.0f, 1.0f + __expf(-x));
}
__device__ __forceinline__ float tanhf_fast(float x) {
    return 1.0f - 2.0f * __fdividef(1.0f, __expf(2.0f * x) + 1.0f);
}
__device__ __forceinline__ void ldsm4(uint32_t* a, uint32_t addr) {
    asm volatile("ldmatrix.sync.aligned.m8n8.x4.shared.b16 {%0,%1,%2,%3},[%4];"
                 : "=r"(a[0]), "=r"(a[1]), "=r"(a[2]), "=r"(a[3]) : "r"(addr));
}
__device__ __forceinline__ void mma16(float* d, const uint32_t* a, uint32_t b0, uint32_t b1) {
    asm volatile(
        "mma.sync.aligned.m16n8k16.row.col.f32.bf16.bf16.f32 "
        "{%0,%1,%2,%3},{%4,%5,%6,%7},{%8,%9},{%0,%1,%2,%3};"
        : "+f"(d[0]), "+f"(d[1]), "+f"(d[2]), "+f"(d[3])
        : "r"(a[0]), "r"(a[1]), "r"(a[2]), "r"(a[3]), "r"(b0), "r"(b1));
}

// ---------------- prep (fold/pack validated in R5/R10 analysis) ----------------
__global__ void prep_basic(const float* W_ih, const float* W_hh, const float* b_ih,
                           const float* b_hh) {
    int idx = blockIdx.x * blockDim.x + threadIdx.x;
    if (idx < 600 * G4) {
        int k = idx / G4, col = idx % G4, u = col >> 2, g = col & 3, n = u + HH * g;
        Wt2_g[idx] = (k < HH) ? W_ih[n * HH + k] : W_hh[n * HH + (k - HH)];
    }
    int i3 = idx - 600 * G4;
    if (i3 >= 0 && i3 < G4) {
        int u = i3 >> 2, g = i3 & 3;
        bias2_g[i3] = b_ih[u + HH * g] + b_hh[u + HH * g];
    }
}
__global__ void prep_fold(const float* W_ih, const float* W_hh, const float* W_out) {
    __shared__ float sw[HH][20];
    int tid = threadIdx.x, kk = tid % 20, c = tid / 20;
    int k = blockIdx.y * 20 + kk, col = blockIdx.x * 16 + c;
    int u = col >> 2, g = col & 3, n = u + HH * g;
    for (int i = tid; i < HH * 20; i += 320)
        sw[i / 20][i % 20] = W_out[(i / 20) * HH + blockIdx.y * 20 + (i % 20)];
    __syncthreads();
    float acc = W_hh[n * HH + k];
    const float* wr = &W_ih[n * HH];
    #pragma unroll 4
    for (int j = 0; j < HH; ++j) acc = fmaf(__ldg(&wr[j]), sw[j][kk], acc);
    Wc2_g[k * G4 + col] = acc;
}
__global__ void prep_biasf(const float* W_ih, const float* b_ih, const float* b_hh,
                           const float* b_out) {
    int col = blockIdx.x * blockDim.x + threadIdx.x;
    if (col >= G4) return;
    int u = col >> 2, g = col & 3, n = u + HH * g;
    float acc = b_ih[n] + b_hh[n];
    const float* wr = &W_ih[n * HH];
    #pragma unroll 4
    for (int j = 0; j < HH; ++j) acc = fmaf(__ldg(&wr[j]), __ldg(&b_out[j]), acc);
    biasf_g[col] = acc;
}
// tiles 0-74 gates (A row r = interleaved col 16t+r), 75-93 out (row = out unit), 94-95 pad
__global__ void prep_pack(const float* W_out) {
    int idx = blockIdx.x * blockDim.x + threadIdx.x;
    if (idx >= 96 * 9728) return;
    int t = idx / 9728, e = idx % 9728;
    int kt = e >> 9, e2 = e & 511, half = e2 >> 8, e3 = e2 & 255, r = e3 >> 4, k16 = e3 & 15;
    int k = kt * 16 + k16;
    float v = 0.f;
    if (t < 75) {
        int c = 16 * t + r;
        if (k < HH) v = Wc2_g[k * G4 + c];
    } else if (t < 94) {
        int n = 16 * (t - 75) + r;
        if (n < HH && k < HH) v = W_out[n * HH + k];
    }
    __nv_bfloat16 hi = __float2bfloat16(v);
    AT_g[idx] = half ? __float2bfloat16(v - __bfloat162float(hi)) : hi;
}
__global__ void reset_bar() { bar_cnt_g = 0u; }

// ---------------- step 0 (K=600, exact fp32) -> h1 (hP1), c1 ----------------
__global__ void __launch_bounds__(320, 1)
step0(const float* h0, const float* c0, const float* start, int B) {
    __shared__ float xh[600 * 8];
    int tid = threadIdx.x, r0 = blockIdx.x * 8;
    for (int idx = tid; idx < HH * 8; idx += 320) {
        int u = idx >> 3, b = idx & 7;
        xh[u * 8 + b] = start[(size_t)(r0 + b) * HH + u];
        xh[(HH + u) * 8 + b] = h0[(size_t)(r0 + b) * HH + u];
    }
    __syncthreads();
    if (tid < HH) {
        float a0[8], a1[8], a2[8], a3[8];
        float4 bb = *(const float4*)&bias2_g[tid * 4];
        #pragma unroll
        for (int b = 0; b < 8; ++b) { a0[b] = bb.x; a1[b] = bb.y; a2[b] = bb.z; a3[b] = bb.w; }
        for (int k = 0; k < 600; ++k) {
            float4 wv = *(const float4*)&Wt2_g[k * G4 + tid * 4];
            #pragma unroll
            for (int b = 0; b < 8; ++b) {
                float xv = xh[k * 8 + b];
                a0[b] = fmaf(xv, wv.x, a0[b]); a1[b] = fmaf(xv, wv.y, a1[b]);
                a2[b] = fmaf(xv, wv.z, a2[b]); a3[b] = fmaf(xv, wv.w, a3[b]);
            }
        }
        #pragma unroll
        for (int b = 0; b < 8; ++b) {
            float iv = sigf(a0[b]), fv = sigf(a1[b]);
            float gv = tanhf_fast(a2[b]), ov = sigf(a3[b]);
            float cc = fmaf(fv, c0[(size_t)(r0 + b) * HH + tid], iv * gv);
            hP1_g[(size_t)(r0 + b) * HH + tid] = ov * tanhf_fast(cc);
            c1_g[(size_t)(r0 + b) * HH + tid] = cc;
        }
    }
}

// ---------------- persistent HMMA kernel ----------------
// 128 CTAs = 8 sets x 16 ranks. rank -> 6 resident tiles; set -> 128 batch rows.
__global__ void __launch_bounds__(NTW, 1)
lstm_hmma(const float* __restrict__ b_out, float* __restrict__ out, int B, int steps) {
    extern __shared__ char sm[];
    const uint32_t sb = smem_u32(sm);
    const int tid = threadIdx.x, wid = tid >> 5, lane = tid & 31;
    const int rank = blockIdx.x & 15;
    const int set = blockIdx.x >> 4;
    const int r0set = set * 128;
    const unsigned NB = gridDim.x;
    float* c_sm = (float*)(sm + SM_C);

    // resident A tiles
    {
        const uint4* src = (const uint4*)(AT_g + (size_t)rank * 6 * 9728);
        uint4* dst = (uint4*)sm;
        for (int i = tid; i < 7296; i += NTW) dst[i] = src[i];
    }
    // zero staging (incl. unit 300-303 pad words, never rewritten -> stays 0)
    for (int i = tid; i < 9728 / 4; i += NTW) ((uint32_t*)(sm + SM_HSTH))[i] = 0;
    // c-state init: this CTA's 24 units x 128 set rows
    for (int i = tid; i < 24 * 128; i += NTW) {
        int ul = i >> 7, ns = i & 127, u = rank * 24 + ul;
        if (u < HH) c_sm[i] = c1_g[(size_t)(r0set + ns) * HH + u];
    }
    __syncthreads();

    const int T = rank * 6 + wid;
    const bool isG = (T < 75), isO = (T >= 75 && T < 94);
    const int q = lane & 3, lr = lane >> 2;
    const bool owner = isG && ((lane & 15) < 4);
    const uint32_t lm_off = (uint32_t)((lane & 15) * 32 + (lane >> 4) * 16);
    const uint32_t Abase = sb + wid * 19456;

    const int uA = 4 * T + ((lane < 16) ? 0 : 1), uB = uA + 2;
    float bG[8];
    if (owner) {
        #pragma unroll
        for (int g = 0; g < 4; ++g) { bG[g] = biasf_g[uA * 4 + g]; bG[4 + g] = biasf_g[uB * 4 + g]; }
    }
    const int n0r = isO ? (16 * (T - 75) + lr) : 0, n1r = n0r + 8;
    const float bo0 = (isO && n0r < HH) ? b_out[n0r] : 0.f;
    const float bo1 = (isO && n1r < HH) ? b_out[n1r] : 0.f;

    for (int j = 1; j <= steps; ++j) {
        const float* hsrc = (j & 1) ? hP1_g : hP0_g;
        float* hdst = (j & 1) ? hP0_g : hP1_g;

        for (int cg = 0; cg < 16; ++cg) {
            // ---- stage chunk: 8 rows x 300 units, fp32 -> bf16 hi/lo in SMEM ----
            for (int i = tid; i < 2400; i += NTW) {
                int n = i / 300, u = i - n * 300;
                float h = hsrc[(size_t)(r0set + cg * 8 + n) * HH + u];
                __nv_bfloat16 hh = __float2bfloat16(h);
                *(__nv_bfloat16*)(sm + SM_HSTH + n * 608 + u * 2) = hh;
                *(__nv_bfloat16*)(sm + SM_HSTL + n * 608 + u * 2) =
                    __float2bfloat16(h - __bfloat162float(hh));
            }
            __syncthreads();

            float d[4] = {0.f, 0.f, 0.f, 0.f};
            if (isG || isO) {
                const char* hstH = sm + SM_HSTH;
                const char* hstL = sm + SM_HSTL;
                #pragma unroll 4
                for (int kt = 0; kt < 19; ++kt) {
                    uint32_t ah[4], al[4];
                    ldsm4(ah, Abase + kt * 1024 + lm_off);
                    ldsm4(al, Abase + kt * 1024 + 512 + lm_off);
                    int u0 = kt * 16 + 2 * q, u1 = u0 + 8;
                    uint32_t bh0 = *(const uint32_t*)(hstH + lr * 608 + u0 * 2);
                    uint32_t bh1 = *(const uint32_t*)(hstH + lr * 608 + u1 * 2);
                    uint32_t bl0 = *(const uint32_t*)(hstL + lr * 608 + u0 * 2);
                    uint32_t bl1 = *(const uint32_t*)(hstL + lr * 608 + u1 * 2);
                    mma16(d, ah, bh0, bh1);
                    mma16(d, ah, bl0, bl1);
                    mma16(d, al, bh0, bh1);
                }
            }
            if (isO) {
                float* orow = out + ((size_t)(j - 1) * B + r0set + cg * 8) * HH;
                if (n0r < HH) {
                    orow[(size_t)(2 * q) * HH + n0r] = d[0] + bo0;
                    orow[(size_t)(2 * q + 1) * HH + n0r] = d[1] + bo0;
                }
                if (n1r < HH) {
                    orow[(size_t)(2 * q) * HH + n1r] = d[2] + bo1;
                    orow[(size_t)(2 * q + 1) * HH + n1r] = d[3] + bo1;
                }
            }
            if (isG && j < steps) {
                float fv[4], gv[4], ov[4];
                #pragma unroll
                for (int p = 0; p < 4; ++p) {
                    fv[p] = __shfl_down_sync(0xffffffffu, d[p], 4);
                    gv[p] = __shfl_down_sync(0xffffffffu, d[p], 8);
                    ov[p] = __shfl_down_sync(0xffffffffu, d[p], 12);
                }
                if (owner) {
                    #pragma unroll
                    for (int c4 = 0; c4 < 4; ++c4) {
                        int ui = c4 >> 1, nn = c4 & 1;
                        int u = ui ? uB : uA;
                        int ns = cg * 8 + 2 * q + nn;
                        float ii = sigf(d[c4] + bG[ui * 4 + 0]);
                        float ff = sigf(fv[c4] + bG[ui * 4 + 1]);
                        float gg = tanhf_fast(gv[c4] + bG[ui * 4 + 2]);
                        float oo = sigf(ov[c4] + bG[ui * 4 + 3]);
                        float* cs = &c_sm[(u - rank * 24) * 128 + ns];
                        float cc = fmaf(ff, *cs, ii * gg);
                        *cs = cc;
                        hdst[(size_t)(r0set + ns) * HH + u] = oo * tanhf_fast(cc);
                    }
                }
            }
            __syncthreads();   // staging reuse
        }

        // ---- grid barrier (monotonic counter; all 128 CTAs co-resident) ----
        __threadfence();
        __syncthreads();
        if (tid == 0) {
            atomicAdd(&bar_cnt_g, 1u);
            unsigned target = NB * (unsigned)j;
            unsigned v;
            do {
                asm volatile("ld.global.acquire.gpu.u32 %0, [%1];"
                             : "=r"(v) : "l"(&bar_cnt_g));
                if (v < target) __nanosleep(64);
            } while (v < target);
        }
        __syncthreads();
    }
}

// ---------------- launch ----------------
extern "C" void kernel_launch(void* const* d_in, const int* in_sizes, int n_in,
                              void* d_out, int out_size) {
    const float* h0 = (const float*)d_in[0];
    const float* c0 = (const float*)d_in[1];
    const float* start = (const float*)d_in[2];
    const float* W_ih = (const float*)d_in[3];
    const float* W_hh = (const float*)d_in[4];
    const float* b_ih = (const float*)d_in[5];
    const float* b_hh = (const float*)d_in[6];
    const float* W_out = (const float*)d_in[7];
    const float* b_out = (const float*)d_in[8];
    int B = in_sizes[0] / HH;            // 1024
    int steps = out_size / (B * HH);     // 256

    int pe = 600 * G4 + G4;
    prep_basic<<<(pe + 255) / 256, 256>>>(W_ih, W_hh, b_ih, b_hh);
    dim3 fg(G4 / 16, HH / 20);
    prep_fold<<<fg, 320>>>(W_ih, W_hh, W_out);
    prep_biasf<<<(G4 + 255) / 256, 256>>>(W_ih, b_ih, b_hh, b_out);
    prep_pack<<<(96 * 9728 + 255) / 256, 256>>>(W_out);
    reset_bar<<<1, 1>>>();
    step0<<<B / 8, 320>>>(h0, c0, start, B);

    cudaFuncSetAttribute(lstm_hmma, cudaFuncAttributeMaxDynamicSharedMemorySize, SM_TOT);
    int grid = 16 * (B / 128);           // 128 CTAs, all co-resident on 148 SMs
    lstm_hmma<<<grid, NTW, SM_TOT>>>(b_out, (float*)d_out, B, steps);
}